// round 16
// baseline (speedup 1.0000x reference)
#include <cstdint>
#include <cuda.h>
#include <cuda_runtime.h>
#include <cuda_bf16.h>

#define DD 512
#define BB 512
#define KT 14

// img_t = tanh(img @ W^T + b)
__device__ float g_x[BB * DD];
// bf16 split operands
__device__ __align__(16) __nv_bfloat16 g_Ahi[BB * DD];
__device__ __align__(16) __nv_bfloat16 g_Alo[BB * DD];
__device__ __align__(16) __nv_bfloat16 g_Whi[DD * DD];
__device__ __align__(16) __nv_bfloat16 g_Wlo[DD * DD];
// grid barrier: monotonic arrival counter (never reset -> graph-replay safe)
__device__ unsigned int g_bar_count = 0;

__constant__ float INVFS[32] = {
    1.0f, 1.0f, 0.5f,
    1.6666666666666666e-1f, 4.1666666666666664e-2f, 8.3333333333333333e-3f,
    1.3888888888888889e-3f, 1.9841269841269841e-4f, 2.4801587301587302e-5f,
    2.7557319223985893e-6f, 2.7557319223985888e-7f, 2.5052108385441720e-8f,
    2.0876756987868100e-9f, 1.6059043836821613e-10f,
    0.0f, 0.0f,
    1.0f, 1.0f, 0.5f,
    1.6666666666666666e-1f, 4.1666666666666664e-2f, 8.3333333333333333e-3f,
    1.3888888888888889e-3f, 1.9841269841269841e-4f, 2.4801587301587302e-5f,
    2.7557319223985893e-6f, 2.7557319223985888e-7f, 2.5052108385441720e-8f,
    2.0876756987868100e-9f, 1.6059043836821613e-10f,
    0.0f, 0.0f
};

typedef unsigned long long ull;

__device__ __forceinline__ ull pk2(float lo, float hi) {
    ull r; asm("mov.b64 %0, {%1,%2};" : "=l"(r) : "f"(lo), "f"(hi)); return r;
}
__device__ __forceinline__ void upk2(ull v, float& lo, float& hi) {
    asm("mov.b64 {%0,%1}, %2;" : "=f"(lo), "=f"(hi) : "l"(v));
}
__device__ __forceinline__ ull fma2(ull a, ull b, ull c) {
    ull d; asm("fma.rn.f32x2 %0, %1, %2, %3;" : "=l"(d) : "l"(a), "l"(b), "l"(c));
    return d;
}
__device__ __forceinline__ ull add2(ull a, ull b) {
    ull d; asm("add.rn.f32x2 %0, %1, %2;" : "=l"(d) : "l"(a), "l"(b)); return d;
}
__device__ __forceinline__ ull mul2(ull a, ull b) {
    ull d; asm("mul.rn.f32x2 %0, %1, %2;" : "=l"(d) : "l"(a), "l"(b)); return d;
}

__device__ __forceinline__ void mma16816(float* c,
    uint32_t a0, uint32_t a1, uint32_t a2, uint32_t a3,
    uint32_t b0, uint32_t b1)
{
    asm volatile(
        "mma.sync.aligned.m16n8k16.row.col.f32.bf16.bf16.f32 "
        "{%0,%1,%2,%3}, {%4,%5,%6,%7}, {%8,%9}, {%0,%1,%2,%3};"
        : "+f"(c[0]), "+f"(c[1]), "+f"(c[2]), "+f"(c[3])
        : "r"(a0), "r"(a1), "r"(a2), "r"(a3), "r"(b0), "r"(b1));
}

__device__ __forceinline__ void ldsm_x4(uint32_t& r0, uint32_t& r1,
                                        uint32_t& r2, uint32_t& r3,
                                        uint32_t saddr)
{
    asm volatile(
        "ldmatrix.sync.aligned.m8n8.x4.shared.b16 {%0,%1,%2,%3}, [%4];"
        : "=r"(r0), "=r"(r1), "=r"(r2), "=r"(r3) : "r"(saddr));
}

__device__ __forceinline__ uint32_t smem_u32(const void* p) {
    uint32_t a;
    asm("{ .reg .u64 t; cvta.to.shared.u64 t, %1; cvt.u32.u64 %0, t; }"
        : "=r"(a) : "l"(p));
    return a;
}

// split float4 -> hi bf16x2 pair + lo bf16x2 pair (packed as uint2 each)
__device__ __forceinline__ void split4(float4 v, uint2& h, uint2& l) {
    __nv_bfloat162 h01 = __floats2bfloat162_rn(v.x, v.y);
    __nv_bfloat162 h23 = __floats2bfloat162_rn(v.z, v.w);
    float rx = v.x - __bfloat162float(__low2bfloat16(h01));
    float ry = v.y - __bfloat162float(__high2bfloat16(h01));
    float rz = v.z - __bfloat162float(__low2bfloat16(h23));
    float rw = v.w - __bfloat162float(__high2bfloat16(h23));
    __nv_bfloat162 l01 = __floats2bfloat162_rn(rx, ry);
    __nv_bfloat162 l23 = __floats2bfloat162_rn(rz, rw);
    h.x = *(uint32_t*)&h01; h.y = *(uint32_t*)&h23;
    l.x = *(uint32_t*)&l01; l.y = *(uint32_t*)&l23;
}

// grid-wide barrier for 512 CTAs (monotonic counter, wrap-safe compare)
__device__ __forceinline__ void grid_barrier512() {
    __threadfence();
    __syncthreads();
    if (threadIdx.x == 0) {
        unsigned ret = atomicAdd(&g_bar_count, 1u);
        unsigned target = (ret & ~511u) + 512u;
        unsigned cur;
        do {
            asm volatile("ld.global.acquire.gpu.u32 %0, [%1];"
                         : "=r"(cur) : "l"(&g_bar_count));
            if ((int)(cur - target) >= 0) break;
            __nanosleep(64);
        } while (true);
    }
    __syncthreads();
}

// ---------------------------------------------------------------------------
// MEGA-KERNEL: convert -> barrier -> GEMM (CTAs 0-127) -> barrier -> coatten.
// Grid 512 x 128 thr. All CTAs resident: smem ~28.4KB (8/SM), regs capped by
// __launch_bounds__(128,4) -> capacity 4*148=592 >= 512.
// ---------------------------------------------------------------------------
#define PITCH 72

__global__ __launch_bounds__(128, 4) void fused_all_kernel(
    const float* __restrict__ A,
    const float* __restrict__ Wm,
    const float* __restrict__ bias,
    const float* __restrict__ audio,
    float* __restrict__ out)
{
    __shared__ __align__(16) __nv_bfloat16 sAhi[64 * PITCH];
    __shared__ __align__(16) __nv_bfloat16 sAlo[64 * PITCH];
    __shared__ __align__(16) __nv_bfloat16 sBhi[32 * PITCH];
    __shared__ __align__(16) __nv_bfloat16 sBlo[32 * PITCH];
    __shared__ float redS[4][33];
    __shared__ float coefA[32];
    __shared__ float coefB[32];

    const int t   = threadIdx.x;
    const int bid = blockIdx.x;          // 0..511

    // ===== phase 1: convert (one float4 of A and W per thread; exact cover) ==
    {
        const int i = bid * 128 + t;     // 0..65535
        float4 va = ((const float4*)A)[i];
        uint2 h, l; split4(va, h, l);
        *(uint2*)&g_Ahi[i * 4] = h;
        *(uint2*)&g_Alo[i * 4] = l;
        float4 vw = ((const float4*)Wm)[i];
        split4(vw, h, l);
        *(uint2*)&g_Whi[i * 4] = h;
        *(uint2*)&g_Wlo[i * 4] = l;
    }
    grid_barrier512();

    // ===== phase 2: GEMM on CTAs 0..127 =====
    if (bid < 128) {
        const int w    = t >> 5;
        const int lane = t & 31;
        const int lq   = lane >> 2;
        const int lr   = lane & 3;
        const int rowBase = (bid >> 4) * 64;
        const int colBase = (bid & 15) * 32;

        const int rA  = (lane & 7) + ((lane >> 3) & 1) * 8;
        const int khA = (lane >> 4) & 1;
        const uint32_t aoff = (uint32_t)((w * 16 + rA) * (PITCH * 2) + khA * 16);
        const int nB  = (lane & 7) + ((lane >> 4) & 1) * 8;
        const int khB = (lane >> 3) & 1;
        const uint32_t boff0 = (uint32_t)(nB * (PITCH * 2) + khB * 16);
        const uint32_t boff1 = boff0 + 16 * (PITCH * 2);

        const uint32_t sbAhi = smem_u32(sAhi);
        const uint32_t sbAlo = smem_u32(sAlo);
        const uint32_t sbBhi = smem_u32(sBhi);
        const uint32_t sbBlo = smem_u32(sBlo);

        float acc[4][4];
        #pragma unroll
        for (int nb = 0; nb < 4; nb++)
            #pragma unroll
            for (int c = 0; c < 4; c++) acc[nb][c] = 0.f;

        uint4 pAh[4], pAl[4], pBh[2], pBl[2];
        #pragma unroll
        for (int rep = 0; rep < 4; rep++) {
            const int i = t + rep * 128, r = i >> 3, j = i & 7;
            const int ge = (rowBase + r) * DD + j * 8;
            pAh[rep] = *(const uint4*)&g_Ahi[ge];
            pAl[rep] = *(const uint4*)&g_Alo[ge];
        }
        #pragma unroll
        for (int rep = 0; rep < 2; rep++) {
            const int i = t + rep * 128, r = i >> 3, j = i & 7;
            const int ge = (colBase + r) * DD + j * 8;
            pBh[rep] = *(const uint4*)&g_Whi[ge];
            pBl[rep] = *(const uint4*)&g_Wlo[ge];
        }

        for (int chunk = 0; chunk < 8; chunk++) {
            #pragma unroll
            for (int rep = 0; rep < 4; rep++) {
                const int i = t + rep * 128, r = i >> 3, j = i & 7;
                *(uint4*)&sAhi[r * PITCH + j * 8] = pAh[rep];
                *(uint4*)&sAlo[r * PITCH + j * 8] = pAl[rep];
            }
            #pragma unroll
            for (int rep = 0; rep < 2; rep++) {
                const int i = t + rep * 128, r = i >> 3, j = i & 7;
                *(uint4*)&sBhi[r * PITCH + j * 8] = pBh[rep];
                *(uint4*)&sBlo[r * PITCH + j * 8] = pBl[rep];
            }
            __syncthreads();

            if (chunk < 7) {
                const int kc = (chunk + 1) * 64;
                #pragma unroll
                for (int rep = 0; rep < 4; rep++) {
                    const int i = t + rep * 128, r = i >> 3, j = i & 7;
                    const int ge = (rowBase + r) * DD + kc + j * 8;
                    pAh[rep] = *(const uint4*)&g_Ahi[ge];
                    pAl[rep] = *(const uint4*)&g_Alo[ge];
                }
                #pragma unroll
                for (int rep = 0; rep < 2; rep++) {
                    const int i = t + rep * 128, r = i >> 3, j = i & 7;
                    const int ge = (colBase + r) * DD + kc + j * 8;
                    pBh[rep] = *(const uint4*)&g_Whi[ge];
                    pBl[rep] = *(const uint4*)&g_Wlo[ge];
                }
            }

            #pragma unroll
            for (int ks = 0; ks < 4; ks++) {
                const uint32_t kb = (uint32_t)(ks * 32);
                uint32_t a0h, a1h, a2h, a3h, a0l, a1l, a2l, a3l;
                ldsm_x4(a0h, a1h, a2h, a3h, sbAhi + aoff + kb);
                ldsm_x4(a0l, a1l, a2l, a3l, sbAlo + aoff + kb);
                uint32_t bh[8], bl[8];
                ldsm_x4(bh[0], bh[1], bh[2], bh[3], sbBhi + boff0 + kb);
                ldsm_x4(bh[4], bh[5], bh[6], bh[7], sbBhi + boff1 + kb);
                ldsm_x4(bl[0], bl[1], bl[2], bl[3], sbBlo + boff0 + kb);
                ldsm_x4(bl[4], bl[5], bl[6], bl[7], sbBlo + boff1 + kb);
                #pragma unroll
                for (int nb = 0; nb < 4; nb++) {
                    mma16816(acc[nb], a0h, a1h, a2h, a3h, bh[nb*2], bh[nb*2+1]);
                    mma16816(acc[nb], a0h, a1h, a2h, a3h, bl[nb*2], bl[nb*2+1]);
                    mma16816(acc[nb], a0l, a1l, a2l, a3l, bh[nb*2], bh[nb*2+1]);
                }
            }
            __syncthreads();
        }

        const int row0 = rowBase + w * 16 + lq;
        const int row1 = row0 + 8;
        #pragma unroll
        for (int nb = 0; nb < 4; nb++) {
            const int col = colBase + nb * 8 + lr * 2;
            const float b0 = bias[col], b1 = bias[col + 1];
            float2 o0, o1;
            o0.x = tanhf(acc[nb][0] + b0); o0.y = tanhf(acc[nb][1] + b1);
            o1.x = tanhf(acc[nb][2] + b0); o1.y = tanhf(acc[nb][3] + b1);
            *(float2*)&g_x[row0 * DD + col] = o0;
            *(float2*)&g_x[row1 * DD + col] = o1;
        }
    }
    grid_barrier512();

    // ===== phase 3: coatten (row = bid), unchanged R9 body =====
    {
        const int wid  = t >> 5;
        const int lane = t & 31;
        const int b    = bid;
        const int idx  = wid * 128 + 4 * lane;

        const float* xrow = g_x   + (size_t)b * DD;
        const float* arow = audio + (size_t)b * DD;
        const float* irow = A     + (size_t)b * DD;   // img
        float* orow = out + (size_t)b * (4 * DD);

        ull x2[2], a2[2];
        {
            ulonglong2 xv = *(const ulonglong2*)&xrow[idx];
            ulonglong2 av = *(const ulonglong2*)&arow[idx];
            x2[0] = xv.x; x2[1] = xv.y;
            a2[0] = av.x; a2[1] = av.y;
            *(ulonglong2*)&orow[idx]      = *(const ulonglong2*)&irow[idx];
            *(ulonglong2*)&orow[DD + idx] = av;
        }

        const ull ONE2 = 0x3F8000003F800000ull;
        float v[32];

        {
            ull svx[2] = {ONE2, ONE2}, sva[2] = {ONE2, ONE2};
            #pragma unroll
            for (int ch = 0; ch < 2; ch++) {
                ull mA[7], pA[7];
                #pragma unroll
                for (int k = 0; k < 7; k++) { mA[k] = 0ull; pA[k] = 0ull; }
                #pragma unroll
                for (int q = 0; q < 2; q++) {
                    ull pwx = svx[q], pwa = sva[q];
                    #pragma unroll
                    for (int k = 0; k < 7; k++) {
                        mA[k] = add2(mA[k], pwx); pwx = mul2(pwx, x2[q]);
                        pA[k] = add2(pA[k], pwa); pwa = mul2(pwa, a2[q]);
                    }
                    svx[q] = pwx; sva[q] = pwa;
                }
                #pragma unroll
                for (int k = 0; k < 7; k++) {
                    float lo, hi;
                    upk2(mA[k], lo, hi); v[ch * 7 + k]      = lo + hi;
                    upk2(pA[k], lo, hi); v[16 + ch * 7 + k] = lo + hi;
                }
            }
            v[14] = 0.f; v[15] = 0.f; v[30] = 0.f; v[31] = 0.f;
        }
        #pragma unroll
        for (int o = 16; o >= 1; o >>= 1) {
            const bool up = (lane & o);
            #pragma unroll
            for (int i = 0; i < o; i++) {
                float send = up ? v[i] : v[i + o];
                float got  = __shfl_xor_sync(0xffffffffu, send, o);
                v[i] = (up ? v[i + o] : v[i]) + got;
            }
        }
        redS[wid][lane] = v[0];
        __syncthreads();
        if (t < 32)
            coefA[t] = (redS[0][t] + redS[1][t] + redS[2][t] + redS[3][t]) * INVFS[t];
        __syncthreads();

        ull w1[2], w2[2];
        {
            float mcR[KT], pcR[KT];
            #pragma unroll
            for (int k = 0; k < KT; k++) { mcR[k] = coefA[k]; pcR[k] = coefA[16 + k]; }
            ull sc[2], sr[2];
            ull tm = pk2(mcR[KT-1], mcR[KT-1]), tp = pk2(pcR[KT-1], pcR[KT-1]);
            sc[0] = tm; sc[1] = tm; sr[0] = tp; sr[1] = tp;
            #pragma unroll
            for (int k = KT - 2; k >= 0; k--) {
                ull cm = pk2(mcR[k], mcR[k]), cp = pk2(pcR[k], pcR[k]);
                #pragma unroll
                for (int q = 0; q < 2; q++) {
                    sc[q] = fma2(sc[q], a2[q], cm);
                    sr[q] = fma2(sr[q], x2[q], cp);
                }
            }
            #pragma unroll
            for (int q = 0; q < 2; q++) {
                float clo, chi, rlo, rhi, alo, ahi, xlo, xhi;
                upk2(sc[q], clo, chi); upk2(a2[q], alo, ahi);
                upk2(sr[q], rlo, rhi); upk2(x2[q], xlo, xhi);
                w1[q] = pk2(__fdividef(alo, clo), __fdividef(ahi, chi));
                w2[q] = pk2(__fdividef(xlo, rlo), __fdividef(xhi, rhi));
            }
        }

        {
            ull svu[2] = {w1[0], w1[1]}, svv[2] = {w2[0], w2[1]};
            #pragma unroll
            for (int ch = 0; ch < 2; ch++) {
                ull uA[7], vA[7];
                #pragma unroll
                for (int k = 0; k < 7; k++) { uA[k] = 0ull; vA[k] = 0ull; }
                #pragma unroll
                for (int q = 0; q < 2; q++) {
                    ull pwu = svu[q], pwv = svv[q];
                    #pragma unroll
                    for (int k = 0; k < 7; k++) {
                        uA[k] = add2(uA[k], pwu); pwu = mul2(pwu, a2[q]);
                        vA[k] = add2(vA[k], pwv); pwv = mul2(pwv, x2[q]);
                    }
                    svu[q] = pwu; svv[q] = pwv;
                }
                #pragma unroll
                for (int k = 0; k < 7; k++) {
                    float lo, hi;
                    upk2(uA[k], lo, hi); v[ch * 7 + k]      = lo + hi;
                    upk2(vA[k], lo, hi); v[16 + ch * 7 + k] = lo + hi;
                }
            }
            v[14] = 0.f; v[15] = 0.f; v[30] = 0.f; v[31] = 0.f;
        }
        #pragma unroll
        for (int o = 16; o >= 1; o >>= 1) {
            const bool up = (lane & o);
            #pragma unroll
            for (int i = 0; i < o; i++) {
                float send = up ? v[i] : v[i + o];
                float got  = __shfl_xor_sync(0xffffffffu, send, o);
                v[i] = (up ? v[i + o] : v[i]) + got;
            }
        }
        redS[wid][lane] = v[0];
        __syncthreads();
        if (t < 32)
            coefB[t] = (redS[0][t] + redS[1][t] + redS[2][t] + redS[3][t]) * INVFS[t];
        __syncthreads();

        {
            float ucR[KT], vcR[KT];
            #pragma unroll
            for (int k = 0; k < KT; k++) { ucR[k] = coefB[k]; vcR[k] = coefB[16 + k]; }
            ull si[2], so[2];
            ull tu = pk2(ucR[KT-1], ucR[KT-1]), tv = pk2(vcR[KT-1], vcR[KT-1]);
            si[0] = tu; si[1] = tu; so[0] = tv; so[1] = tv;
            #pragma unroll
            for (int k = KT - 2; k >= 0; k--) {
                ull cu = pk2(ucR[k], ucR[k]), cv = pk2(vcR[k], vcR[k]);
                #pragma unroll
                for (int q = 0; q < 2; q++) {
                    si[q] = fma2(si[q], x2[q], cu);
                    so[q] = fma2(so[q], a2[q], cv);
                }
            }
            ulonglong2 vi; vi.x = si[0]; vi.y = si[1];
            ulonglong2 vo; vo.x = so[0]; vo.y = so[1];
            *(ulonglong2*)&orow[2 * DD + idx] = vi;
            *(ulonglong2*)&orow[3 * DD + idx] = vo;
        }
    }
}

extern "C" void kernel_launch(void* const* d_in, const int* in_sizes, int n_in,
                              void* d_out, int out_size)
{
    const float* img   = (const float*)d_in[0];
    const float* audio = (const float*)d_in[1];
    const float* W     = (const float*)d_in[2];
    const float* bias  = (const float*)d_in[3];
    float* out = (float*)d_out;

    fused_all_kernel<<<512, 128>>>(img, W, bias, audio, out);
}

// round 17
// speedup vs baseline: 1.2727x; 1.2727x over previous
#include <cstdint>
#include <cuda.h>
#include <cuda_runtime.h>
#include <cuda_bf16.h>

#define DD 512
#define BB 512
#define KT 14

// img_t = tanh(img @ W^T + b)
__device__ float g_x[BB * DD];
// bf16 split operands
__device__ __align__(16) __nv_bfloat16 g_Ahi[BB * DD];
__device__ __align__(16) __nv_bfloat16 g_Alo[BB * DD];
__device__ __align__(16) __nv_bfloat16 g_Whi[DD * DD];
__device__ __align__(16) __nv_bfloat16 g_Wlo[DD * DD];
// grid barrier: monotonic arrival counter (never reset -> graph-replay safe)
__device__ unsigned int g_bar_count = 0;

__constant__ float INVFS[32] = {
    1.0f, 1.0f, 0.5f,
    1.6666666666666666e-1f, 4.1666666666666664e-2f, 8.3333333333333333e-3f,
    1.3888888888888889e-3f, 1.9841269841269841e-4f, 2.4801587301587302e-5f,
    2.7557319223985893e-6f, 2.7557319223985888e-7f, 2.5052108385441720e-8f,
    2.0876756987868100e-9f, 1.6059043836821613e-10f,
    0.0f, 0.0f,
    1.0f, 1.0f, 0.5f,
    1.6666666666666666e-1f, 4.1666666666666664e-2f, 8.3333333333333333e-3f,
    1.3888888888888889e-3f, 1.9841269841269841e-4f, 2.4801587301587302e-5f,
    2.7557319223985893e-6f, 2.7557319223985888e-7f, 2.5052108385441720e-8f,
    2.0876756987868100e-9f, 1.6059043836821613e-10f,
    0.0f, 0.0f
};

typedef unsigned long long ull;

__device__ __forceinline__ ull pk2(float lo, float hi) {
    ull r; asm("mov.b64 %0, {%1,%2};" : "=l"(r) : "f"(lo), "f"(hi)); return r;
}
__device__ __forceinline__ void upk2(ull v, float& lo, float& hi) {
    asm("mov.b64 {%0,%1}, %2;" : "=f"(lo), "=f"(hi) : "l"(v));
}
__device__ __forceinline__ ull fma2(ull a, ull b, ull c) {
    ull d; asm("fma.rn.f32x2 %0, %1, %2, %3;" : "=l"(d) : "l"(a), "l"(b), "l"(c));
    return d;
}
__device__ __forceinline__ ull add2(ull a, ull b) {
    ull d; asm("add.rn.f32x2 %0, %1, %2;" : "=l"(d) : "l"(a), "l"(b)); return d;
}
__device__ __forceinline__ ull mul2(ull a, ull b) {
    ull d; asm("mul.rn.f32x2 %0, %1, %2;" : "=l"(d) : "l"(a), "l"(b)); return d;
}

__device__ __forceinline__ void mma16816(float* c,
    uint32_t a0, uint32_t a1, uint32_t a2, uint32_t a3,
    uint32_t b0, uint32_t b1)
{
    asm volatile(
        "mma.sync.aligned.m16n8k16.row.col.f32.bf16.bf16.f32 "
        "{%0,%1,%2,%3}, {%4,%5,%6,%7}, {%8,%9}, {%0,%1,%2,%3};"
        : "+f"(c[0]), "+f"(c[1]), "+f"(c[2]), "+f"(c[3])
        : "r"(a0), "r"(a1), "r"(a2), "r"(a3), "r"(b0), "r"(b1));
}

__device__ __forceinline__ void ldsm_x4(uint32_t& r0, uint32_t& r1,
                                        uint32_t& r2, uint32_t& r3,
                                        uint32_t saddr)
{
    asm volatile(
        "ldmatrix.sync.aligned.m8n8.x4.shared.b16 {%0,%1,%2,%3}, [%4];"
        : "=r"(r0), "=r"(r1), "=r"(r2), "=r"(r3) : "r"(saddr));
}

__device__ __forceinline__ uint32_t smem_u32(const void* p) {
    uint32_t a;
    asm("{ .reg .u64 t; cvta.to.shared.u64 t, %1; cvt.u32.u64 %0, t; }"
        : "=r"(a) : "l"(p));
    return a;
}

// split float4 -> hi bf16x2 pair + lo bf16x2 pair (packed as uint2 each)
__device__ __forceinline__ void split4(float4 v, uint2& h, uint2& l) {
    __nv_bfloat162 h01 = __floats2bfloat162_rn(v.x, v.y);
    __nv_bfloat162 h23 = __floats2bfloat162_rn(v.z, v.w);
    float rx = v.x - __bfloat162float(__low2bfloat16(h01));
    float ry = v.y - __bfloat162float(__high2bfloat16(h01));
    float rz = v.z - __bfloat162float(__low2bfloat16(h23));
    float rw = v.w - __bfloat162float(__high2bfloat16(h23));
    __nv_bfloat162 l01 = __floats2bfloat162_rn(rx, ry);
    __nv_bfloat162 l23 = __floats2bfloat162_rn(rz, rw);
    h.x = *(uint32_t*)&h01; h.y = *(uint32_t*)&h23;
    l.x = *(uint32_t*)&l01; l.y = *(uint32_t*)&l23;
}

// ---------------------------------------------------------------------------
// Kernel 1: FUSED convert + grid-barrier + split-bf16 GEMM — EXACT R15 version
// (proven 9.7us incl. overhead; NO launch-bounds reg cap -> no spills).
// ---------------------------------------------------------------------------
#define PITCH 72

__global__ __launch_bounds__(128) void gemm_fused_kernel(
    const float* __restrict__ A,
    const float* __restrict__ Wm,
    const float* __restrict__ bias)
{
    __shared__ __align__(16) __nv_bfloat16 sAhi[64 * PITCH];
    __shared__ __align__(16) __nv_bfloat16 sAlo[64 * PITCH];
    __shared__ __align__(16) __nv_bfloat16 sBhi[32 * PITCH];
    __shared__ __align__(16) __nv_bfloat16 sBlo[32 * PITCH];

    const int t    = threadIdx.x;
    const int bid  = blockIdx.y * 16 + blockIdx.x;   // 0..127
    const int gtid = bid * 128 + t;                  // 0..16383

    // phase 1: convert (disjoint slices; 4 float4 per tensor/thread)
    #pragma unroll
    for (int rep = 0; rep < 4; rep++) {
        const int i = gtid + rep * 16384;
        float4 va = ((const float4*)A)[i];
        uint2 h, l; split4(va, h, l);
        *(uint2*)&g_Ahi[i * 4] = h;
        *(uint2*)&g_Alo[i * 4] = l;
        float4 vw = ((const float4*)Wm)[i];
        split4(vw, h, l);
        *(uint2*)&g_Whi[i * 4] = h;
        *(uint2*)&g_Wlo[i * 4] = l;
    }

    // phase 2: grid barrier (128 CTAs, monotonic counter)
    __threadfence();
    __syncthreads();
    if (t == 0) {
        unsigned ret = atomicAdd(&g_bar_count, 1u);
        unsigned target = (ret & ~127u) + 128u;
        unsigned cur;
        do {
            asm volatile("ld.global.acquire.gpu.u32 %0, [%1];"
                         : "=r"(cur) : "l"(&g_bar_count));
            if ((int)(cur - target) >= 0) break;
            __nanosleep(64);
        } while (true);
    }
    __syncthreads();

    // phase 3: GEMM (identical to R14/R15)
    const int w    = t >> 5;
    const int lane = t & 31;
    const int lq   = lane >> 2;
    const int lr   = lane & 3;
    const int rowBase = blockIdx.y * 64;
    const int colBase = blockIdx.x * 32;

    const int rA  = (lane & 7) + ((lane >> 3) & 1) * 8;
    const int khA = (lane >> 4) & 1;
    const uint32_t aoff = (uint32_t)((w * 16 + rA) * (PITCH * 2) + khA * 16);
    const int nB  = (lane & 7) + ((lane >> 4) & 1) * 8;
    const int khB = (lane >> 3) & 1;
    const uint32_t boff0 = (uint32_t)(nB * (PITCH * 2) + khB * 16);
    const uint32_t boff1 = boff0 + 16 * (PITCH * 2);

    const uint32_t sbAhi = smem_u32(sAhi);
    const uint32_t sbAlo = smem_u32(sAlo);
    const uint32_t sbBhi = smem_u32(sBhi);
    const uint32_t sbBlo = smem_u32(sBlo);

    float acc[4][4];
    #pragma unroll
    for (int nb = 0; nb < 4; nb++)
        #pragma unroll
        for (int c = 0; c < 4; c++) acc[nb][c] = 0.f;

    uint4 pAh[4], pAl[4], pBh[2], pBl[2];
    #pragma unroll
    for (int rep = 0; rep < 4; rep++) {
        const int i = t + rep * 128, r = i >> 3, j = i & 7;
        const int ge = (rowBase + r) * DD + j * 8;
        pAh[rep] = *(const uint4*)&g_Ahi[ge];
        pAl[rep] = *(const uint4*)&g_Alo[ge];
    }
    #pragma unroll
    for (int rep = 0; rep < 2; rep++) {
        const int i = t + rep * 128, r = i >> 3, j = i & 7;
        const int ge = (colBase + r) * DD + j * 8;
        pBh[rep] = *(const uint4*)&g_Whi[ge];
        pBl[rep] = *(const uint4*)&g_Wlo[ge];
    }

    for (int chunk = 0; chunk < 8; chunk++) {
        #pragma unroll
        for (int rep = 0; rep < 4; rep++) {
            const int i = t + rep * 128, r = i >> 3, j = i & 7;
            *(uint4*)&sAhi[r * PITCH + j * 8] = pAh[rep];
            *(uint4*)&sAlo[r * PITCH + j * 8] = pAl[rep];
        }
        #pragma unroll
        for (int rep = 0; rep < 2; rep++) {
            const int i = t + rep * 128, r = i >> 3, j = i & 7;
            *(uint4*)&sBhi[r * PITCH + j * 8] = pBh[rep];
            *(uint4*)&sBlo[r * PITCH + j * 8] = pBl[rep];
        }
        __syncthreads();

        if (chunk < 7) {
            const int kc = (chunk + 1) * 64;
            #pragma unroll
            for (int rep = 0; rep < 4; rep++) {
                const int i = t + rep * 128, r = i >> 3, j = i & 7;
                const int ge = (rowBase + r) * DD + kc + j * 8;
                pAh[rep] = *(const uint4*)&g_Ahi[ge];
                pAl[rep] = *(const uint4*)&g_Alo[ge];
            }
            #pragma unroll
            for (int rep = 0; rep < 2; rep++) {
                const int i = t + rep * 128, r = i >> 3, j = i & 7;
                const int ge = (colBase + r) * DD + kc + j * 8;
                pBh[rep] = *(const uint4*)&g_Whi[ge];
                pBl[rep] = *(const uint4*)&g_Wlo[ge];
            }
        }

        #pragma unroll
        for (int ks = 0; ks < 4; ks++) {
            const uint32_t kb = (uint32_t)(ks * 32);
            uint32_t a0h, a1h, a2h, a3h, a0l, a1l, a2l, a3l;
            ldsm_x4(a0h, a1h, a2h, a3h, sbAhi + aoff + kb);
            ldsm_x4(a0l, a1l, a2l, a3l, sbAlo + aoff + kb);
            uint32_t bh[8], bl[8];
            ldsm_x4(bh[0], bh[1], bh[2], bh[3], sbBhi + boff0 + kb);
            ldsm_x4(bh[4], bh[5], bh[6], bh[7], sbBhi + boff1 + kb);
            ldsm_x4(bl[0], bl[1], bl[2], bl[3], sbBlo + boff0 + kb);
            ldsm_x4(bl[4], bl[5], bl[6], bl[7], sbBlo + boff1 + kb);
            #pragma unroll
            for (int nb = 0; nb < 4; nb++) {
                mma16816(acc[nb], a0h, a1h, a2h, a3h, bh[nb*2], bh[nb*2+1]);
                mma16816(acc[nb], a0h, a1h, a2h, a3h, bl[nb*2], bl[nb*2+1]);
                mma16816(acc[nb], a0l, a1l, a2l, a3l, bh[nb*2], bh[nb*2+1]);
            }
        }
        __syncthreads();
    }

    const int row0 = rowBase + w * 16 + lq;
    const int row1 = row0 + 8;
    #pragma unroll
    for (int nb = 0; nb < 4; nb++) {
        const int col = colBase + nb * 8 + lr * 2;
        const float b0 = bias[col], b1 = bias[col + 1];
        float2 o0, o1;
        o0.x = tanhf(acc[nb][0] + b0); o0.y = tanhf(acc[nb][1] + b1);
        o1.x = tanhf(acc[nb][2] + b0); o1.y = tanhf(acc[nb][3] + b1);
        *(float2*)&g_x[row0 * DD + col] = o0;
        *(float2*)&g_x[row1 * DD + col] = o1;
    }
}

// ---------------------------------------------------------------------------
// Kernel 2: co-attention, 8 warps/row (256 thr), grid 512.
// Lane owns ONE f32x2 pair (q=1): idx = wid*64 + 2*lane.
// Per-warp scatter-butterfly -> smem combine across 8 warps.
// ---------------------------------------------------------------------------
__global__ __launch_bounds__(256, 1) void coatten_kernel(
    const float* __restrict__ img,
    const float* __restrict__ audio,
    float* __restrict__ out)
{
    const int t    = threadIdx.x;
    const int wid  = t >> 5;          // 0..7
    const int lane = t & 31;
    const int b    = blockIdx.x;
    const int idx  = wid * 64 + 2 * lane;

    __shared__ float redS[8][33];
    __shared__ float coefA[32];
    __shared__ float coefB[32];

    const float* xrow = g_x   + (size_t)b * DD;
    const float* arow = audio + (size_t)b * DD;
    const float* irow = img   + (size_t)b * DD;
    float* orow = out + (size_t)b * (4 * DD);

    ull x2, a2;
    {
        x2 = *(const ull*)&xrow[idx];
        a2 = *(const ull*)&arow[idx];
        *(ull*)&orow[idx]      = *(const ull*)&irow[idx];
        *(ull*)&orow[DD + idx] = a2;
    }

    const ull ONE2 = 0x3F8000003F800000ull;
    float v[32];

    // ===== phase A: partial moments m_k = sum x^k, p_k = sum a^k (q=1) =====
    {
        ull pwx = ONE2, pwa = ONE2;
        #pragma unroll
        for (int ch = 0; ch < 2; ch++) {
            #pragma unroll
            for (int k = 0; k < 7; k++) {
                float lo, hi;
                upk2(pwx, lo, hi); v[ch * 7 + k]      = lo + hi;
                upk2(pwa, lo, hi); v[16 + ch * 7 + k] = lo + hi;
                pwx = mul2(pwx, x2);
                pwa = mul2(pwa, a2);
            }
        }
        v[14] = 0.f; v[15] = 0.f; v[30] = 0.f; v[31] = 0.f;
    }
    // scatter-butterfly: lane L ends owning slot L in v[0]
    #pragma unroll
    for (int o = 16; o >= 1; o >>= 1) {
        const bool up = (lane & o);
        #pragma unroll
        for (int i = 0; i < o; i++) {
            float send = up ? v[i] : v[i + o];
            float got  = __shfl_xor_sync(0xffffffffu, send, o);
            v[i] = (up ? v[i + o] : v[i]) + got;
        }
    }
    redS[wid][lane] = v[0];
    __syncthreads();
    if (t < 32)
        coefA[t] = (redS[0][t] + redS[1][t] + redS[2][t] + redS[3][t] +
                    redS[4][t] + redS[5][t] + redS[6][t] + redS[7][t]) * INVFS[t];
    __syncthreads();

    // Horner: c_j = eval(mc at a_j), r_i = eval(pc at x_i) -> w1, w2
    ull w1, w2;
    {
        float mcR[KT], pcR[KT];
        #pragma unroll
        for (int k = 0; k < KT; k++) { mcR[k] = coefA[k]; pcR[k] = coefA[16 + k]; }
        ull sc = pk2(mcR[KT-1], mcR[KT-1]);
        ull sr = pk2(pcR[KT-1], pcR[KT-1]);
        #pragma unroll
        for (int k = KT - 2; k >= 0; k--) {
            sc = fma2(sc, a2, pk2(mcR[k], mcR[k]));
            sr = fma2(sr, x2, pk2(pcR[k], pcR[k]));
        }
        float clo, chi, rlo, rhi, alo, ahi, xlo, xhi;
        upk2(sc, clo, chi); upk2(a2, alo, ahi);
        upk2(sr, rlo, rhi); upk2(x2, xlo, xhi);
        w1 = pk2(__fdividef(alo, clo), __fdividef(ahi, chi));
        w2 = pk2(__fdividef(xlo, rlo), __fdividef(xhi, rhi));
    }

    // ===== phase B: u_k = sum w1 a^k, v_k = sum w2 x^k (q=1) =====
    {
        ull pwu = w1, pwv = w2;
        #pragma unroll
        for (int ch = 0; ch < 2; ch++) {
            #pragma unroll
            for (int k = 0; k < 7; k++) {
                float lo, hi;
                upk2(pwu, lo, hi); v[ch * 7 + k]      = lo + hi;
                upk2(pwv, lo, hi); v[16 + ch * 7 + k] = lo + hi;
                pwu = mul2(pwu, a2);
                pwv = mul2(pwv, x2);
            }
        }
        v[14] = 0.f; v[15] = 0.f; v[30] = 0.f; v[31] = 0.f;
    }
    #pragma unroll
    for (int o = 16; o >= 1; o >>= 1) {
        const bool up = (lane & o);
        #pragma unroll
        for (int i = 0; i < o; i++) {
            float send = up ? v[i] : v[i + o];
            float got  = __shfl_xor_sync(0xffffffffu, send, o);
            v[i] = (up ? v[i + o] : v[i]) + got;
        }
    }
    redS[wid][lane] = v[0];
    __syncthreads();
    if (t < 32)
        coefB[t] = (redS[0][t] + redS[1][t] + redS[2][t] + redS[3][t] +
                    redS[4][t] + redS[5][t] + redS[6][t] + redS[7][t]) * INVFS[t];
    __syncthreads();

    // Horner: C_img = eval(uc at x), C_audio = eval(vc at a); store
    {
        float ucR[KT], vcR[KT];
        #pragma unroll
        for (int k = 0; k < KT; k++) { ucR[k] = coefB[k]; vcR[k] = coefB[16 + k]; }
        ull si = pk2(ucR[KT-1], ucR[KT-1]);
        ull so = pk2(vcR[KT-1], vcR[KT-1]);
        #pragma unroll
        for (int k = KT - 2; k >= 0; k--) {
            si = fma2(si, x2, pk2(ucR[k], ucR[k]));
            so = fma2(so, a2, pk2(vcR[k], vcR[k]));
        }
        *(ull*)&orow[2 * DD + idx] = si;
        *(ull*)&orow[3 * DD + idx] = so;
    }
}

extern "C" void kernel_launch(void* const* d_in, const int* in_sizes, int n_in,
                              void* d_out, int out_size)
{
    const float* img   = (const float*)d_in[0];
    const float* audio = (const float*)d_in[1];
    const float* W     = (const float*)d_in[2];
    const float* bias  = (const float*)d_in[3];
    float* out = (float*)d_out;

    gemm_fused_kernel<<<dim3(16, 8), 128>>>(img, W, bias);
    coatten_kernel<<<512, 256>>>(img, audio, out);
}